// round 11
// baseline (speedup 1.0000x reference)
#include <cuda_runtime.h>
#include <cuda_fp16.h>
#include <cstdint>

#define N_NODES 50000
#define N_EDGES 800000
#define D_IN    128
#define D_HID   128
#define D_OUT   64

// -------- device scratch (allocation-free rule: __device__ globals) --------
__device__ __align__(16) half g_support[N_NODES * D_HID];  // GEMM out (fp16)
__device__ __align__(16) half g_h[N_NODES * D_HID];        // activations (fp16)
__device__ int   g_row_ptr[N_NODES + 1];
__device__ int   g_counts[N_NODES];    // zero-init at load; scan restores zeros
__device__ int   g_cursor[N_NODES];
__device__ __align__(16) uint2 g_edge[N_EDGES];            // (col, val) packed

// W images: fp16 hi/lo, W^T layout [n][k] with rows padded to 136 halfs.
#define WROW 136
__device__ __align__(16) half g_wimg[2 * 128 * WROW + 2 * 128 * WROW + 2 * 64 * WROW];

// ============================ CSR construction ==============================
// NOTE: no zero_kernel. g_counts is zero at module load, and scan_kernel
// writes zeros back after reading, so counts are zero at every hist start.

__global__ void hist_kernel(const int* __restrict__ edge_row) {
    int i = blockIdx.x * blockDim.x + threadIdx.x;      // i < E/4
    if (i < N_EDGES / 4) {
        int4 r = ((const int4*)edge_row)[i];
        atomicAdd(&g_counts[r.x], 1);
        atomicAdd(&g_counts[r.y], 1);
        atomicAdd(&g_counts[r.z], 1);
        atomicAdd(&g_counts[r.w], 1);
    }
}

// single-block exclusive scan, int4 per thread; seeds g_cursor = row_ptr and
// restores g_counts to zero for the next call / graph replay.
__global__ void scan_kernel() {
    __shared__ int warp_sums[32];
    __shared__ int carry_s;
    const int tid  = threadIdx.x;
    const int lane = tid & 31;
    const int wid  = tid >> 5;
    if (tid == 0) carry_s = 0;
    __syncthreads();
    int4* c4 = (int4*)g_counts;
    const int N4 = N_NODES / 4;
    for (int base = 0; base < N4; base += 1024) {
        int i = base + tid;
        int4 v = (i < N4) ? c4[i] : make_int4(0, 0, 0, 0);
        if (i < N4) c4[i] = make_int4(0, 0, 0, 0);   // restore zeros
        int s = v.x + v.y + v.z + v.w;
        int incl = s;
        #pragma unroll
        for (int off = 1; off < 32; off <<= 1) {
            int t = __shfl_up_sync(0xffffffffu, incl, off);
            if (lane >= off) incl += t;
        }
        if (lane == 31) warp_sums[wid] = incl;
        __syncthreads();
        if (wid == 0) {
            int ws = warp_sums[lane];
            int wincl = ws;
            #pragma unroll
            for (int off = 1; off < 32; off <<= 1) {
                int t = __shfl_up_sync(0xffffffffu, wincl, off);
                if (lane >= off) wincl += t;
            }
            warp_sums[lane] = wincl - ws;
        }
        __syncthreads();
        int carry = carry_s;
        int excl = carry + warp_sums[wid] + incl - s;
        if (i < N4) {
            int4 o;
            o.x = excl;
            o.y = excl + v.x;
            o.z = o.y + v.y;
            o.w = o.z + v.z;
            *(int4*)&g_row_ptr[4 * i] = o;
            *(int4*)&g_cursor[4 * i]  = o;
        }
        __syncthreads();
        if (tid == 1023) carry_s = carry + warp_sums[31] + incl;
        __syncthreads();
    }
    if (tid == 0) g_row_ptr[N_NODES] = carry_s;
}

__global__ void scatter_kernel(const int* __restrict__ edge_row,
                               const int* __restrict__ edge_col,
                               const float* __restrict__ edge_val) {
    int i = blockIdx.x * blockDim.x + threadIdx.x;      // i < E/4
    if (i < N_EDGES / 4) {
        int4   r = ((const int4*)edge_row)[i];
        int4   c = ((const int4*)edge_col)[i];
        float4 v = ((const float4*)edge_val)[i];
        int p0 = atomicAdd(&g_cursor[r.x], 1);
        g_edge[p0] = make_uint2((uint32_t)c.x, __float_as_uint(v.x));
        int p1 = atomicAdd(&g_cursor[r.y], 1);
        g_edge[p1] = make_uint2((uint32_t)c.y, __float_as_uint(v.y));
        int p2 = atomicAdd(&g_cursor[r.z], 1);
        g_edge[p2] = make_uint2((uint32_t)c.z, __float_as_uint(v.z));
        int p3 = atomicAdd(&g_cursor[r.w], 1);
        g_edge[p3] = make_uint2((uint32_t)c.w, __float_as_uint(v.w));
    }
}

// ====================== W image prep (all layers) ===========================

__device__ __forceinline__ void w_split_store(const float* W, half* img,
                                              int NC, int idx) {
    int k = idx / NC;
    int n = idx % NC;
    float v = W[idx];
    half hi = __float2half_rn(v);
    half lo = __float2half_rn(v - __half2float(hi));
    img[n * WROW + k] = hi;
    img[NC * WROW + n * WROW + k] = lo;
}

__global__ void prep_w_all_kernel(const float* __restrict__ W1,
                                  const float* __restrict__ W2,
                                  const float* __restrict__ W3,
                                  half* __restrict__ img1,
                                  half* __restrict__ img2,
                                  half* __restrict__ img3) {
    int idx = blockIdx.x * blockDim.x + threadIdx.x;    // < 16384
    if (idx < 128 * 128) {
        w_split_store(W1, img1, 128, idx);
        w_split_store(W2, img2, 128, idx);
    }
    if (idx < 128 * 64)
        w_split_store(W3, img3, 64, idx);
}

// ============================ HMMA GEMM =====================================

__device__ __forceinline__ void mma16816(float* d,
                                         uint32_t a0, uint32_t a1, uint32_t a2, uint32_t a3,
                                         uint32_t b0, uint32_t b1) {
    asm volatile(
        "mma.sync.aligned.m16n8k16.row.col.f32.f16.f16.f32 "
        "{%0,%1,%2,%3}, {%4,%5,%6,%7}, {%8,%9}, {%0,%1,%2,%3};"
        : "+f"(d[0]), "+f"(d[1]), "+f"(d[2]), "+f"(d[3])
        : "r"(a0), "r"(a1), "r"(a2), "r"(a3), "r"(b0), "r"(b1));
}

__device__ __forceinline__ void ldsm_x4(uint32_t& r0, uint32_t& r1,
                                        uint32_t& r2, uint32_t& r3,
                                        uint32_t addr) {
    asm volatile("ldmatrix.sync.aligned.m8n8.x4.shared.b16 {%0,%1,%2,%3}, [%4];"
                 : "=r"(r0), "=r"(r1), "=r"(r2), "=r"(r3) : "r"(addr));
}

__device__ __forceinline__ uint32_t smem_u32(const void* p) {
    return (uint32_t)__cvta_generic_to_shared(p);
}

template <int NC, bool AFP32>
__global__ void __launch_bounds__(256, 1)
gemm_mma_kernel(const void* __restrict__ Aptr, const half* __restrict__ Wimg,
                half* __restrict__ C, int M) {
    extern __shared__ __align__(16) char smem_raw[];
    half* Wh = (half*)smem_raw;              // [NC][WROW]
    half* Wl = Wh + NC * WROW;
    half* Ah = Wl + NC * WROW;               // [128][WROW]
    half* Al = Ah + 128 * WROW;              // only used if AFP32

    const int tid = threadIdx.x;

    {
        const uint4* src = (const uint4*)Wimg;
        uint4* dst = (uint4*)Wh;
        constexpr int n16 = 2 * NC * WROW * 2 / 16;
        #pragma unroll 4
        for (int i = tid; i < n16; i += 256) dst[i] = src[i];
    }

    {
        const int r  = tid >> 1;
        const int c0 = (tid & 1) * 64;
        const int gr = blockIdx.x * 128 + r;
        const bool valid = (gr < M);
        if (AFP32) {
            const float4* src = (const float4*)((const float*)Aptr + (size_t)gr * 128 + c0);
            #pragma unroll
            for (int j = 0; j < 16; j++) {
                float4 v = valid ? src[j] : make_float4(0.f, 0.f, 0.f, 0.f);
                half hx = __float2half_rn(v.x), hy = __float2half_rn(v.y);
                half hz = __float2half_rn(v.z), hw = __float2half_rn(v.w);
                half lx = __float2half_rn(v.x - __half2float(hx));
                half ly = __float2half_rn(v.y - __half2float(hy));
                half lz = __float2half_rn(v.z - __half2float(hz));
                half lw = __float2half_rn(v.w - __half2float(hw));
                int base = r * WROW + c0 + j * 4;
                *(half2*)&Ah[base]     = __halves2half2(hx, hy);
                *(half2*)&Ah[base + 2] = __halves2half2(hz, hw);
                *(half2*)&Al[base]     = __halves2half2(lx, ly);
                *(half2*)&Al[base + 2] = __halves2half2(lz, lw);
            }
        } else {
            const uint4* src = (const uint4*)((const half*)Aptr + (size_t)gr * 128 + c0);
            #pragma unroll
            for (int j = 0; j < 8; j++) {
                uint4 v = valid ? src[j] : make_uint4(0u, 0u, 0u, 0u);
                *(uint4*)&Ah[r * WROW + c0 + j * 8] = v;
            }
        }
    }
    __syncthreads();

    const int warp = tid >> 5;
    const int lane = tid & 31;
    const int qr = lane >> 2;
    const int qc = (lane & 3) * 2;
    const int mrow = warp * 16;

    // ldmatrix per-lane source addresses.
    // A x4 tiles: t0=a0(rows mrow+0..7, k..k+7)  t1=a1(rows+8, k)
    //             t2=a2(rows, k+8)               t3=a3(rows+8, k+8)
    // B x4 tiles: t0=b0(ntile n0, k)  t1=b1(n0, k+8)
    //             t2=b0(ntile n0+8,k) t3=b1(n0+8, k+8)
    const int lrow = lane & 7;
    const int lsel = lane >> 3;     // 0..3 -> tile index
    const uint32_t aBaseH = smem_u32(
        &Ah[(mrow + lrow + (lsel & 1) * 8) * WROW + (lsel >> 1) * 8]);
    const uint32_t aBaseL = AFP32 ? smem_u32(
        &Al[(mrow + lrow + (lsel & 1) * 8) * WROW + (lsel >> 1) * 8]) : 0u;
    const uint32_t bBaseH = smem_u32(
        &Wh[(lrow + (lsel >> 1) * 8) * WROW + (lsel & 1) * 8]);
    const uint32_t bBaseL = smem_u32(
        &Wl[(lrow + (lsel >> 1) * 8) * WROW + (lsel & 1) * 8]);

    constexpr int NT = NC / 8;
    float acc[NT][4];
    #pragma unroll
    for (int nt = 0; nt < NT; nt++)
        #pragma unroll
        for (int j = 0; j < 4; j++) acc[nt][j] = 0.f;

    #pragma unroll
    for (int ks = 0; ks < 8; ks++) {
        const uint32_t koff = ks * 32;           // 16 halfs * 2B
        uint32_t ah0, ah1, ah2, ah3;
        ldsm_x4(ah0, ah1, ah2, ah3, aBaseH + koff);
        uint32_t al0 = 0, al1 = 0, al2 = 0, al3 = 0;
        if (AFP32)
            ldsm_x4(al0, al1, al2, al3, aBaseL + koff);

        #pragma unroll
        for (int nt = 0; nt < NT; nt += 2) {
            const uint32_t noff = (uint32_t)nt * 8 * WROW * 2;
            uint32_t bh0, bh1, bh2, bh3;
            uint32_t bl0, bl1, bl2, bl3;
            ldsm_x4(bh0, bh1, bh2, bh3, bBaseH + noff + koff);
            ldsm_x4(bl0, bl1, bl2, bl3, bBaseL + noff + koff);
            mma16816(acc[nt],     ah0, ah1, ah2, ah3, bh0, bh1);
            mma16816(acc[nt],     ah0, ah1, ah2, ah3, bl0, bl1);
            if (AFP32)
                mma16816(acc[nt], al0, al1, al2, al3, bh0, bh1);
            mma16816(acc[nt + 1],     ah0, ah1, ah2, ah3, bh2, bh3);
            mma16816(acc[nt + 1],     ah0, ah1, ah2, ah3, bl2, bl3);
            if (AFP32)
                mma16816(acc[nt + 1], al0, al1, al2, al3, bh2, bh3);
        }
    }

    const int grow = blockIdx.x * 128 + mrow + qr;
    #pragma unroll
    for (int nt = 0; nt < NT; nt++) {
        const int col = nt * 8 + qc;
        if (grow < M)
            *(half2*)&C[(size_t)grow * NC + col] =
                __floats2half2_rn(acc[nt][0], acc[nt][1]);
        if (grow + 8 < M)
            *(half2*)&C[(size_t)(grow + 8) * NC + col] =
                __floats2half2_rn(acc[nt][2], acc[nt][3]);
    }
}

// ================================ SpMM ======================================
// warp-per-row segmented sum; 2-way unrolled edge loop (known-best).

template <int D, bool RELU, bool OUT_HALF>
__global__ void spmm_kernel(const half* __restrict__ S,
                            const float* __restrict__ bias,
                            void* __restrict__ outp, int N) {
    constexpr int F = D / 32;                 // halfs per lane (4 or 2)
    const int warp = (blockIdx.x * blockDim.x + threadIdx.x) >> 5;
    const int lane = threadIdx.x & 31;
    if (warp >= N) return;

    const int start = g_row_ptr[warp];
    const int end   = g_row_ptr[warp + 1];

    float acc0[F], acc1[F];
    #pragma unroll
    for (int j = 0; j < F; j++) { acc0[j] = 0.0f; acc1[j] = 0.0f; }

    int e = start;
    #pragma unroll 2
    for (; e + 1 < end; e += 2) {
        uint2 pr0 = __ldg(&g_edge[e]);
        uint2 pr1 = __ldg(&g_edge[e + 1]);
        float v0 = __uint_as_float(pr0.y);
        float v1 = __uint_as_float(pr1.y);
        if (F == 4) {
            uint2 p0 = *(const uint2*)&S[(size_t)(int)pr0.x * D + lane * 4];
            uint2 p1 = *(const uint2*)&S[(size_t)(int)pr1.x * D + lane * 4];
            float2 a0 = __half22float2(*(half2*)&p0.x);
            float2 b0 = __half22float2(*(half2*)&p0.y);
            float2 a1 = __half22float2(*(half2*)&p1.x);
            float2 b1 = __half22float2(*(half2*)&p1.y);
            acc0[0] += v0 * a0.x; acc0[1] += v0 * a0.y;
            acc0[2] += v0 * b0.x; acc0[3] += v0 * b0.y;
            acc1[0] += v1 * a1.x; acc1[1] += v1 * a1.y;
            acc1[2] += v1 * b1.x; acc1[3] += v1 * b1.y;
        } else {
            uint32_t p0 = *(const uint32_t*)&S[(size_t)(int)pr0.x * D + lane * 2];
            uint32_t p1 = *(const uint32_t*)&S[(size_t)(int)pr1.x * D + lane * 2];
            float2 a0 = __half22float2(*(half2*)&p0);
            float2 a1 = __half22float2(*(half2*)&p1);
            acc0[0] += v0 * a0.x; acc0[1] += v0 * a0.y;
            acc1[0] += v1 * a1.x; acc1[1] += v1 * a1.y;
        }
    }
    if (e < end) {
        uint2 pr = __ldg(&g_edge[e]);
        float v = __uint_as_float(pr.y);
        if (F == 4) {
            uint2 p = *(const uint2*)&S[(size_t)(int)pr.x * D + lane * 4];
            float2 a = __half22float2(*(half2*)&p.x);
            float2 b = __half22float2(*(half2*)&p.y);
            acc0[0] += v * a.x; acc0[1] += v * a.y;
            acc0[2] += v * b.x; acc0[3] += v * b.y;
        } else {
            uint32_t p = *(const uint32_t*)&S[(size_t)(int)pr.x * D + lane * 2];
            float2 a = __half22float2(*(half2*)&p);
            acc0[0] += v * a.x; acc0[1] += v * a.y;
        }
    }

    float acc[F];
    #pragma unroll
    for (int j = 0; j < F; j++) {
        float r = acc0[j] + acc1[j] + __ldg(&bias[lane * F + j]);
        if (RELU) r = fmaxf(r, 0.0f);
        acc[j] = r;
    }

    if (OUT_HALF) {
        half* out = (half*)outp;
        if (F == 4) {
            half2 h0 = __floats2half2_rn(acc[0], acc[1]);
            half2 h1 = __floats2half2_rn(acc[2], acc[3]);
            *(uint2*)&out[(size_t)warp * D + lane * 4] =
                make_uint2(*(uint32_t*)&h0, *(uint32_t*)&h1);
        } else {
            half2 h0 = __floats2half2_rn(acc[0], acc[1]);
            *(uint32_t*)&out[(size_t)warp * D + lane * 2] = *(uint32_t*)&h0;
        }
    } else {
        float* out = (float*)outp;
        if (F == 4)
            *(float4*)&out[(size_t)warp * D + lane * 4] =
                make_float4(acc[0], acc[1], acc[2], acc[3]);
        else
            *(float2*)&out[(size_t)warp * D + lane * 2] =
                make_float2(acc[0], acc[1]);
    }
}

// ============================== launch =====================================

extern "C" void kernel_launch(void* const* d_in, const int* in_sizes, int n_in,
                              void* d_out, int out_size) {
    const float* x        = (const float*)d_in[0];
    const int*   edge_row = (const int*)  d_in[1];
    const int*   edge_col = (const int*)  d_in[2];
    const float* edge_val = (const float*)d_in[3];
    const float* W1       = (const float*)d_in[4];
    const float* b1       = (const float*)d_in[5];
    const float* W2       = (const float*)d_in[6];
    const float* b2       = (const float*)d_in[7];
    const float* W3       = (const float*)d_in[8];
    const float* b3       = (const float*)d_in[9];

    const int N = N_NODES;
    const int E = N_EDGES;

    half* support; cudaGetSymbolAddress((void**)&support, g_support);
    half* h;       cudaGetSymbolAddress((void**)&h, g_h);
    half* wimg;    cudaGetSymbolAddress((void**)&wimg, g_wimg);
    half* wimg1 = wimg;
    half* wimg2 = wimg + 2 * 128 * WROW;
    half* wimg3 = wimg + 4 * 128 * WROW;

    const int SMEM_L1 = (2 * 128 + 2 * 128) * WROW * 2;  // 139264
    const int SMEM_L2 = (2 * 128 + 128) * WROW * 2;      // 104448
    const int SMEM_L3 = (2 * 64 + 128) * WROW * 2;       //  69632
    cudaFuncSetAttribute((const void*)gemm_mma_kernel<128, true>,
                         cudaFuncAttributeMaxDynamicSharedMemorySize, SMEM_L1);
    cudaFuncSetAttribute((const void*)gemm_mma_kernel<128, false>,
                         cudaFuncAttributeMaxDynamicSharedMemorySize, SMEM_L2);
    cudaFuncSetAttribute((const void*)gemm_mma_kernel<64, false>,
                         cudaFuncAttributeMaxDynamicSharedMemorySize, SMEM_L3);

    // side stream + events for CSR/GEMM1 overlap (created per call; not
    // destroyed — kernel_launch runs only a few times and destroying a
    // forked stream during capture can invalidate the capture).
    cudaStream_t s2;
    cudaEvent_t ev_fork, ev_join;
    cudaStreamCreateWithFlags(&s2, cudaStreamNonBlocking);
    cudaEventCreateWithFlags(&ev_fork, cudaEventDisableTiming);
    cudaEventCreateWithFlags(&ev_join, cudaEventDisableTiming);

    // fork immediately: CSR chain (hist->scan->scatter) on s2,
    // W-image prep + GEMM1 on main stream. The chains are independent.
    cudaEventRecord(ev_fork, 0);
    cudaStreamWaitEvent(s2, ev_fork, 0);
    hist_kernel<<<(E / 4 + 255) / 256, 256, 0, s2>>>(edge_row);
    scan_kernel<<<1, 1024, 0, s2>>>();
    scatter_kernel<<<(E / 4 + 255) / 256, 256, 0, s2>>>(edge_row, edge_col, edge_val);
    cudaEventRecord(ev_join, s2);

    const int gemm_grid = (N + 127) / 128;   // 391
    const int spmm_grid = (N + 7) / 8;

    prep_w_all_kernel<<<64, 256>>>(W1, W2, W3, wimg1, wimg2, wimg3);
    gemm_mma_kernel<128, true><<<gemm_grid, 256, SMEM_L1>>>(x, wimg1, support, N);

    // join: SpMM1 needs both GEMM1 (main) and CSR (s2)
    cudaStreamWaitEvent(0, ev_join, 0);

    spmm_kernel<128, true, true><<<spmm_grid, 256>>>(support, b1, h, N);

    gemm_mma_kernel<128, false><<<gemm_grid, 256, SMEM_L2>>>(h, wimg2, support, N);
    spmm_kernel<128, true, true><<<spmm_grid, 256>>>(support, b2, h, N);

    gemm_mma_kernel<64, false><<<gemm_grid, 256, SMEM_L3>>>(h, wimg3, support, N);
    spmm_kernel<64, false, false><<<spmm_grid, 256>>>(support, b3, d_out, N);
}

// round 12
// speedup vs baseline: 1.0411x; 1.0411x over previous
#include <cuda_runtime.h>
#include <cuda_fp16.h>
#include <cstdint>

#define N_NODES 50000
#define N_EDGES 800000
#define D_IN    128
#define D_HID   128
#define D_OUT   64
#define CHUNK0_ROWS 25088            // 196 gemm tiles; chunk1 = rest

// -------- device scratch (allocation-free rule: __device__ globals) --------
__device__ __align__(16) half g_support[N_NODES * D_HID];  // GEMM out (fp16)
__device__ __align__(16) half g_h[N_NODES * D_HID];        // activations (fp16)
__device__ int   g_row_ptr[N_NODES + 1];
__device__ int   g_counts[N_NODES];    // zero-init at load; scan restores zeros
__device__ int   g_cursor[N_NODES];
__device__ __align__(16) uint2 g_edge[N_EDGES];            // (col, val) packed

// W images: fp16 hi/lo, W^T layout [n][k] with rows padded to 136 halfs.
#define WROW 136
__device__ __align__(16) half g_wimg[2 * 128 * WROW + 2 * 128 * WROW + 2 * 64 * WROW];

// ============================ CSR construction ==============================
// NOTE: no zero_kernel. g_counts is zero at module load, and scan_kernel
// writes zeros back after reading, so counts are zero at every hist start.

__global__ void hist_kernel(const int* __restrict__ edge_row) {
    int i = blockIdx.x * blockDim.x + threadIdx.x;      // i < E/4
    if (i < N_EDGES / 4) {
        int4 r = ((const int4*)edge_row)[i];
        atomicAdd(&g_counts[r.x], 1);
        atomicAdd(&g_counts[r.y], 1);
        atomicAdd(&g_counts[r.z], 1);
        atomicAdd(&g_counts[r.w], 1);
    }
}

// single-block exclusive scan, int4 per thread; seeds g_cursor = row_ptr and
// restores g_counts to zero for the next call / graph replay.
__global__ void scan_kernel() {
    __shared__ int warp_sums[32];
    __shared__ int carry_s;
    const int tid  = threadIdx.x;
    const int lane = tid & 31;
    const int wid  = tid >> 5;
    if (tid == 0) carry_s = 0;
    __syncthreads();
    int4* c4 = (int4*)g_counts;
    const int N4 = N_NODES / 4;
    for (int base = 0; base < N4; base += 1024) {
        int i = base + tid;
        int4 v = (i < N4) ? c4[i] : make_int4(0, 0, 0, 0);
        if (i < N4) c4[i] = make_int4(0, 0, 0, 0);   // restore zeros
        int s = v.x + v.y + v.z + v.w;
        int incl = s;
        #pragma unroll
        for (int off = 1; off < 32; off <<= 1) {
            int t = __shfl_up_sync(0xffffffffu, incl, off);
            if (lane >= off) incl += t;
        }
        if (lane == 31) warp_sums[wid] = incl;
        __syncthreads();
        if (wid == 0) {
            int ws = warp_sums[lane];
            int wincl = ws;
            #pragma unroll
            for (int off = 1; off < 32; off <<= 1) {
                int t = __shfl_up_sync(0xffffffffu, wincl, off);
                if (lane >= off) wincl += t;
            }
            warp_sums[lane] = wincl - ws;
        }
        __syncthreads();
        int carry = carry_s;
        int excl = carry + warp_sums[wid] + incl - s;
        if (i < N4) {
            int4 o;
            o.x = excl;
            o.y = excl + v.x;
            o.z = o.y + v.y;
            o.w = o.z + v.z;
            *(int4*)&g_row_ptr[4 * i] = o;
            *(int4*)&g_cursor[4 * i]  = o;
        }
        __syncthreads();
        if (tid == 1023) carry_s = carry + warp_sums[31] + incl;
        __syncthreads();
    }
    if (tid == 0) g_row_ptr[N_NODES] = carry_s;
}

__global__ void scatter_kernel(const int* __restrict__ edge_row,
                               const int* __restrict__ edge_col,
                               const float* __restrict__ edge_val) {
    int i = blockIdx.x * blockDim.x + threadIdx.x;      // i < E/4
    if (i < N_EDGES / 4) {
        int4   r = ((const int4*)edge_row)[i];
        int4   c = ((const int4*)edge_col)[i];
        float4 v = ((const float4*)edge_val)[i];
        int p0 = atomicAdd(&g_cursor[r.x], 1);
        g_edge[p0] = make_uint2((uint32_t)c.x, __float_as_uint(v.x));
        int p1 = atomicAdd(&g_cursor[r.y], 1);
        g_edge[p1] = make_uint2((uint32_t)c.y, __float_as_uint(v.y));
        int p2 = atomicAdd(&g_cursor[r.z], 1);
        g_edge[p2] = make_uint2((uint32_t)c.z, __float_as_uint(v.z));
        int p3 = atomicAdd(&g_cursor[r.w], 1);
        g_edge[p3] = make_uint2((uint32_t)c.w, __float_as_uint(v.w));
    }
}

// ====================== W image prep (all layers) ===========================

__device__ __forceinline__ void w_split_store(const float* W, half* img,
                                              int NC, int idx) {
    int k = idx / NC;
    int n = idx % NC;
    float v = W[idx];
    half hi = __float2half_rn(v);
    half lo = __float2half_rn(v - __half2float(hi));
    img[n * WROW + k] = hi;
    img[NC * WROW + n * WROW + k] = lo;
}

__global__ void prep_w_all_kernel(const float* __restrict__ W1,
                                  const float* __restrict__ W2,
                                  const float* __restrict__ W3,
                                  half* __restrict__ img1,
                                  half* __restrict__ img2,
                                  half* __restrict__ img3) {
    int idx = blockIdx.x * blockDim.x + threadIdx.x;    // < 16384
    if (idx < 128 * 128) {
        w_split_store(W1, img1, 128, idx);
        w_split_store(W2, img2, 128, idx);
    }
    if (idx < 128 * 64)
        w_split_store(W3, img3, 64, idx);
}

// ============================ HMMA GEMM =====================================

__device__ __forceinline__ void mma16816(float* d,
                                         uint32_t a0, uint32_t a1, uint32_t a2, uint32_t a3,
                                         uint32_t b0, uint32_t b1) {
    asm volatile(
        "mma.sync.aligned.m16n8k16.row.col.f32.f16.f16.f32 "
        "{%0,%1,%2,%3}, {%4,%5,%6,%7}, {%8,%9}, {%0,%1,%2,%3};"
        : "+f"(d[0]), "+f"(d[1]), "+f"(d[2]), "+f"(d[3])
        : "r"(a0), "r"(a1), "r"(a2), "r"(a3), "r"(b0), "r"(b1));
}

__device__ __forceinline__ void ldsm_x4(uint32_t& r0, uint32_t& r1,
                                        uint32_t& r2, uint32_t& r3,
                                        uint32_t addr) {
    asm volatile("ldmatrix.sync.aligned.m8n8.x4.shared.b16 {%0,%1,%2,%3}, [%4];"
                 : "=r"(r0), "=r"(r1), "=r"(r2), "=r"(r3) : "r"(addr));
}

__device__ __forceinline__ uint32_t smem_u32(const void* p) {
    return (uint32_t)__cvta_generic_to_shared(p);
}

// rows processed: row_base + blockIdx.x*128 + r, bounded by M.
template <int NC, bool AFP32>
__global__ void __launch_bounds__(256, 1)
gemm_mma_kernel(const void* __restrict__ Aptr, const half* __restrict__ Wimg,
                half* __restrict__ C, int M, int row_base) {
    extern __shared__ __align__(16) char smem_raw[];
    half* Wh = (half*)smem_raw;              // [NC][WROW]
    half* Wl = Wh + NC * WROW;
    half* Ah = Wl + NC * WROW;               // [128][WROW]
    half* Al = Ah + 128 * WROW;              // only used if AFP32

    const int tid = threadIdx.x;
    const int tile_row0 = row_base + blockIdx.x * 128;

    {
        const uint4* src = (const uint4*)Wimg;
        uint4* dst = (uint4*)Wh;
        constexpr int n16 = 2 * NC * WROW * 2 / 16;
        #pragma unroll 4
        for (int i = tid; i < n16; i += 256) dst[i] = src[i];
    }

    {
        const int r  = tid >> 1;
        const int c0 = (tid & 1) * 64;
        const int gr = tile_row0 + r;
        const bool valid = (gr < M);
        if (AFP32) {
            const float4* src = (const float4*)((const float*)Aptr + (size_t)gr * 128 + c0);
            #pragma unroll
            for (int j = 0; j < 16; j++) {
                float4 v = valid ? src[j] : make_float4(0.f, 0.f, 0.f, 0.f);
                half hx = __float2half_rn(v.x), hy = __float2half_rn(v.y);
                half hz = __float2half_rn(v.z), hw = __float2half_rn(v.w);
                half lx = __float2half_rn(v.x - __half2float(hx));
                half ly = __float2half_rn(v.y - __half2float(hy));
                half lz = __float2half_rn(v.z - __half2float(hz));
                half lw = __float2half_rn(v.w - __half2float(hw));
                int base = r * WROW + c0 + j * 4;
                *(half2*)&Ah[base]     = __halves2half2(hx, hy);
                *(half2*)&Ah[base + 2] = __halves2half2(hz, hw);
                *(half2*)&Al[base]     = __halves2half2(lx, ly);
                *(half2*)&Al[base + 2] = __halves2half2(lz, lw);
            }
        } else {
            const uint4* src = (const uint4*)((const half*)Aptr + (size_t)gr * 128 + c0);
            #pragma unroll
            for (int j = 0; j < 8; j++) {
                uint4 v = valid ? src[j] : make_uint4(0u, 0u, 0u, 0u);
                *(uint4*)&Ah[r * WROW + c0 + j * 8] = v;
            }
        }
    }
    __syncthreads();

    const int warp = tid >> 5;
    const int lane = tid & 31;
    const int qr = lane >> 2;
    const int qc = (lane & 3) * 2;
    const int mrow = warp * 16;

    const int lrow = lane & 7;
    const int lsel = lane >> 3;     // 0..3 -> tile index
    const uint32_t aBaseH = smem_u32(
        &Ah[(mrow + lrow + (lsel & 1) * 8) * WROW + (lsel >> 1) * 8]);
    const uint32_t aBaseL = AFP32 ? smem_u32(
        &Al[(mrow + lrow + (lsel & 1) * 8) * WROW + (lsel >> 1) * 8]) : 0u;
    const uint32_t bBaseH = smem_u32(
        &Wh[(lrow + (lsel >> 1) * 8) * WROW + (lsel & 1) * 8]);
    const uint32_t bBaseL = smem_u32(
        &Wl[(lrow + (lsel >> 1) * 8) * WROW + (lsel & 1) * 8]);

    constexpr int NT = NC / 8;
    float acc[NT][4];
    #pragma unroll
    for (int nt = 0; nt < NT; nt++)
        #pragma unroll
        for (int j = 0; j < 4; j++) acc[nt][j] = 0.f;

    #pragma unroll
    for (int ks = 0; ks < 8; ks++) {
        const uint32_t koff = ks * 32;           // 16 halfs * 2B
        uint32_t ah0, ah1, ah2, ah3;
        ldsm_x4(ah0, ah1, ah2, ah3, aBaseH + koff);
        uint32_t al0 = 0, al1 = 0, al2 = 0, al3 = 0;
        if (AFP32)
            ldsm_x4(al0, al1, al2, al3, aBaseL + koff);

        #pragma unroll
        for (int nt = 0; nt < NT; nt += 2) {
            const uint32_t noff = (uint32_t)nt * 8 * WROW * 2;
            uint32_t bh0, bh1, bh2, bh3;
            uint32_t bl0, bl1, bl2, bl3;
            ldsm_x4(bh0, bh1, bh2, bh3, bBaseH + noff + koff);
            ldsm_x4(bl0, bl1, bl2, bl3, bBaseL + noff + koff);
            mma16816(acc[nt],     ah0, ah1, ah2, ah3, bh0, bh1);
            mma16816(acc[nt],     ah0, ah1, ah2, ah3, bl0, bl1);
            if (AFP32)
                mma16816(acc[nt], al0, al1, al2, al3, bh0, bh1);
            mma16816(acc[nt + 1],     ah0, ah1, ah2, ah3, bh2, bh3);
            mma16816(acc[nt + 1],     ah0, ah1, ah2, ah3, bl2, bl3);
            if (AFP32)
                mma16816(acc[nt + 1], al0, al1, al2, al3, bh2, bh3);
        }
    }

    const int grow = tile_row0 + mrow + qr;
    #pragma unroll
    for (int nt = 0; nt < NT; nt++) {
        const int col = nt * 8 + qc;
        if (grow < M)
            *(half2*)&C[(size_t)grow * NC + col] =
                __floats2half2_rn(acc[nt][0], acc[nt][1]);
        if (grow + 8 < M)
            *(half2*)&C[(size_t)(grow + 8) * NC + col] =
                __floats2half2_rn(acc[nt][2], acc[nt][3]);
    }
}

// ================================ SpMM ======================================
// warp-per-row segmented sum; 2-way unrolled edge loop (known-best).
// processes rows [row_base, row_end).

template <int D, bool RELU, bool OUT_HALF>
__global__ void spmm_kernel(const half* __restrict__ S,
                            const float* __restrict__ bias,
                            void* __restrict__ outp,
                            int row_base, int row_end) {
    constexpr int F = D / 32;                 // halfs per lane (4 or 2)
    const int warp = row_base +
        ((blockIdx.x * blockDim.x + threadIdx.x) >> 5);
    const int lane = threadIdx.x & 31;
    if (warp >= row_end) return;

    const int start = g_row_ptr[warp];
    const int end   = g_row_ptr[warp + 1];

    float acc0[F], acc1[F];
    #pragma unroll
    for (int j = 0; j < F; j++) { acc0[j] = 0.0f; acc1[j] = 0.0f; }

    int e = start;
    #pragma unroll 2
    for (; e + 1 < end; e += 2) {
        uint2 pr0 = __ldg(&g_edge[e]);
        uint2 pr1 = __ldg(&g_edge[e + 1]);
        float v0 = __uint_as_float(pr0.y);
        float v1 = __uint_as_float(pr1.y);
        if (F == 4) {
            uint2 p0 = *(const uint2*)&S[(size_t)(int)pr0.x * D + lane * 4];
            uint2 p1 = *(const uint2*)&S[(size_t)(int)pr1.x * D + lane * 4];
            float2 a0 = __half22float2(*(half2*)&p0.x);
            float2 b0 = __half22float2(*(half2*)&p0.y);
            float2 a1 = __half22float2(*(half2*)&p1.x);
            float2 b1 = __half22float2(*(half2*)&p1.y);
            acc0[0] += v0 * a0.x; acc0[1] += v0 * a0.y;
            acc0[2] += v0 * b0.x; acc0[3] += v0 * b0.y;
            acc1[0] += v1 * a1.x; acc1[1] += v1 * a1.y;
            acc1[2] += v1 * b1.x; acc1[3] += v1 * b1.y;
        } else {
            uint32_t p0 = *(const uint32_t*)&S[(size_t)(int)pr0.x * D + lane * 2];
            uint32_t p1 = *(const uint32_t*)&S[(size_t)(int)pr1.x * D + lane * 2];
            float2 a0 = __half22float2(*(half2*)&p0);
            float2 a1 = __half22float2(*(half2*)&p1);
            acc0[0] += v0 * a0.x; acc0[1] += v0 * a0.y;
            acc1[0] += v1 * a1.x; acc1[1] += v1 * a1.y;
        }
    }
    if (e < end) {
        uint2 pr = __ldg(&g_edge[e]);
        float v = __uint_as_float(pr.y);
        if (F == 4) {
            uint2 p = *(const uint2*)&S[(size_t)(int)pr.x * D + lane * 4];
            float2 a = __half22float2(*(half2*)&p.x);
            float2 b = __half22float2(*(half2*)&p.y);
            acc0[0] += v * a.x; acc0[1] += v * a.y;
            acc0[2] += v * b.x; acc0[3] += v * b.y;
        } else {
            uint32_t p = *(const uint32_t*)&S[(size_t)(int)pr.x * D + lane * 2];
            float2 a = __half22float2(*(half2*)&p);
            acc0[0] += v * a.x; acc0[1] += v * a.y;
        }
    }

    float acc[F];
    #pragma unroll
    for (int j = 0; j < F; j++) {
        float r = acc0[j] + acc1[j] + __ldg(&bias[lane * F + j]);
        if (RELU) r = fmaxf(r, 0.0f);
        acc[j] = r;
    }

    if (OUT_HALF) {
        half* out = (half*)outp;
        if (F == 4) {
            half2 h0 = __floats2half2_rn(acc[0], acc[1]);
            half2 h1 = __floats2half2_rn(acc[2], acc[3]);
            *(uint2*)&out[(size_t)warp * D + lane * 4] =
                make_uint2(*(uint32_t*)&h0, *(uint32_t*)&h1);
        } else {
            half2 h0 = __floats2half2_rn(acc[0], acc[1]);
            *(uint32_t*)&out[(size_t)warp * D + lane * 2] = *(uint32_t*)&h0;
        }
    } else {
        float* out = (float*)outp;
        if (F == 4)
            *(float4*)&out[(size_t)warp * D + lane * 4] =
                make_float4(acc[0], acc[1], acc[2], acc[3]);
        else
            *(float2*)&out[(size_t)warp * D + lane * 2] =
                make_float2(acc[0], acc[1]);
    }
}

// ============================== launch =====================================

extern "C" void kernel_launch(void* const* d_in, const int* in_sizes, int n_in,
                              void* d_out, int out_size) {
    const float* x        = (const float*)d_in[0];
    const int*   edge_row = (const int*)  d_in[1];
    const int*   edge_col = (const int*)  d_in[2];
    const float* edge_val = (const float*)d_in[3];
    const float* W1       = (const float*)d_in[4];
    const float* b1       = (const float*)d_in[5];
    const float* W2       = (const float*)d_in[6];
    const float* b2       = (const float*)d_in[7];
    const float* W3       = (const float*)d_in[8];
    const float* b3       = (const float*)d_in[9];

    const int N = N_NODES;
    const int E = N_EDGES;

    half* support; cudaGetSymbolAddress((void**)&support, g_support);
    half* h;       cudaGetSymbolAddress((void**)&h, g_h);
    half* wimg;    cudaGetSymbolAddress((void**)&wimg, g_wimg);
    half* wimg1 = wimg;
    half* wimg2 = wimg + 2 * 128 * WROW;
    half* wimg3 = wimg + 4 * 128 * WROW;

    const int SMEM_L1 = (2 * 128 + 2 * 128) * WROW * 2;  // 139264
    const int SMEM_L2 = (2 * 128 + 128) * WROW * 2;      // 104448
    const int SMEM_L3 = (2 * 64 + 128) * WROW * 2;       //  69632
    cudaFuncSetAttribute((const void*)gemm_mma_kernel<128, true>,
                         cudaFuncAttributeMaxDynamicSharedMemorySize, SMEM_L1);
    cudaFuncSetAttribute((const void*)gemm_mma_kernel<128, false>,
                         cudaFuncAttributeMaxDynamicSharedMemorySize, SMEM_L2);
    cudaFuncSetAttribute((const void*)gemm_mma_kernel<64, false>,
                         cudaFuncAttributeMaxDynamicSharedMemorySize, SMEM_L3);

    // side stream + events (created per call; intentionally not destroyed —
    // kernel_launch runs only a few times; destroying a forked stream during
    // capture can invalidate the capture).
    cudaStream_t s2;
    cudaEvent_t ev_fork, ev_csr, ev_g1, ev_b, ev_c, ev_d;
    cudaStreamCreateWithFlags(&s2, cudaStreamNonBlocking);
    cudaEventCreateWithFlags(&ev_fork, cudaEventDisableTiming);
    cudaEventCreateWithFlags(&ev_csr,  cudaEventDisableTiming);
    cudaEventCreateWithFlags(&ev_g1,   cudaEventDisableTiming);
    cudaEventCreateWithFlags(&ev_b,    cudaEventDisableTiming);
    cudaEventCreateWithFlags(&ev_c,    cudaEventDisableTiming);
    cudaEventCreateWithFlags(&ev_d,    cudaEventDisableTiming);

    // chunk geometry
    const int R0 = CHUNK0_ROWS;                 // rows [0, R0) = chunk 0
    const int tiles0 = R0 / 128;                // 196
    const int tiles1 = (N - R0 + 127) / 128;    // 195
    const int sgrid0 = (R0 + 7) / 8;
    const int sgrid1 = (N - R0 + 7) / 8;
    const int spmm_grid_full = (N + 7) / 8;

    // ---- fork: CSR on s2 ; prep + GEMM1 on main ----
    cudaEventRecord(ev_fork, 0);
    cudaStreamWaitEvent(s2, ev_fork, 0);
    hist_kernel<<<(E / 4 + 255) / 256, 256, 0, s2>>>(edge_row);
    scan_kernel<<<1, 1024, 0, s2>>>();
    scatter_kernel<<<(E / 4 + 255) / 256, 256, 0, s2>>>(edge_row, edge_col, edge_val);
    // (CSR results stay in s2 program order for s2's spmm chunks)

    prep_w_all_kernel<<<64, 256>>>(W1, W2, W3, wimg1, wimg2, wimg3);
    gemm_mma_kernel<128, true><<<(N + 127) / 128, 256, SMEM_L1>>>(
        x, wimg1, support, N, 0);
    cudaEventRecord(ev_g1, 0);                  // gemm1 (+prep) done
    cudaEventRecord(ev_csr, s2);                // CSR done

    // ---- layer 1 spmm + layer 2 gemm, chunked ----
    cudaStreamWaitEvent(0, ev_csr, 0);          // main: needs CSR (has gemm1)
    cudaStreamWaitEvent(s2, ev_g1, 0);          // s2: needs gemm1 (has CSR)

    spmm_kernel<128, true, true><<<sgrid0, 256>>>(support, b1, h, 0, R0);
    gemm_mma_kernel<128, false><<<tiles0, 256, SMEM_L2>>>(h, wimg2, support, N, 0);

    spmm_kernel<128, true, true><<<sgrid1, 256, 0, s2>>>(support, b1, h, R0, N);
    gemm_mma_kernel<128, false><<<tiles1, 256, SMEM_L2, s2>>>(h, wimg2, support, N, R0);
    cudaEventRecord(ev_b, s2);                  // gemm2 chunk1 done

    cudaEventRecord(ev_c, 0);                   // gemm2 chunk0 done

    // ---- layer 2 spmm + layer 3 gemm, chunked ----
    cudaStreamWaitEvent(0, ev_b, 0);            // main: needs gemm2_c1
    cudaStreamWaitEvent(s2, ev_c, 0);           // s2: needs gemm2_c0

    spmm_kernel<128, true, true><<<sgrid0, 256>>>(support, b2, h, 0, R0);
    gemm_mma_kernel<64, false><<<tiles0, 256, SMEM_L3>>>(h, wimg3, support, N, 0);

    spmm_kernel<128, true, true><<<sgrid1, 256, 0, s2>>>(support, b2, h, R0, N);
    gemm_mma_kernel<64, false><<<tiles1, 256, SMEM_L3, s2>>>(h, wimg3, support, N, R0);
    cudaEventRecord(ev_d, s2);                  // gemm3 chunk1 done

    // ---- final spmm (full, needs all of gemm3) ----
    cudaStreamWaitEvent(0, ev_d, 0);
    spmm_kernel<64, false, false><<<spmm_grid_full, 256>>>(support, b3, d_out, 0, N);
}